// round 3
// baseline (speedup 1.0000x reference)
#include <cuda_runtime.h>
#include <float.h>

// TropConv2D: out[pos, f] = max_k(p_k + w[k][f]) - min_k(p_k + w[k][f]) + bias[f]
// pos flat over (b, ho, wo); p_k = x[b, ho+i, wo+j, c], k = (i*3+j)*32 + c
#define KH 3
#define KW 3
#define CH 32
#define NF 64
#define HH 32
#define WW 32
#define HO 30
#define WO 30
#define KK  (KH*KW*CH)       // 288
#define NPOS (8*HO*WO)       // 7200

#define WT_STRIDE 292                       // padded k-stride per filter row (floats)
#define WT_FLOATS (NF*WT_STRIDE)            // 18688
#define XSEG_FLOATS (3*WW*CH)               // 3072 (one contiguous 3-row triple)
#define X_S_FLOATS (2*XSEG_FLOATS)          // 6144
#define SMEM_FLOATS (WT_FLOATS + X_S_FLOATS)
#define SMEM_BYTES (SMEM_FLOATS*4)          // 99328

#define NTHREADS 192     // 8 fg x 24 pp
#define NCTA 296         // 2 * 148  -> exactly 2 CTAs per SM
#define BASE_CNT 24      // 200 CTAs get 24 positions, 96 get 25 (96*25+200*24=7200)

__device__ __forceinline__ float2 fadd2(float2 a, float2 b) {
    float2 r;
    asm("add.rn.f32x2 %0, %1, %2;"
        : "=l"(reinterpret_cast<unsigned long long&>(r))
        : "l"(reinterpret_cast<unsigned long long&>(a)),
          "l"(reinterpret_cast<unsigned long long&>(b)));
    return r;
}

__global__ __launch_bounds__(NTHREADS, 2)
void tropconv_kernel(const float* __restrict__ x,
                     const float* __restrict__ w,
                     const float* __restrict__ bias,
                     float* __restrict__ out)
{
    extern __shared__ float smem[];
    float* w_t = smem;                 // [NF][WT_STRIDE], w_t[f*292 + k] = w[k*64+f]
    float* x_s = smem + WT_FLOATS;     // [2][3][WW][CH] two row-triples

    const int tid = threadIdx.x;
    const int cta = blockIdx.x;

    const int cnt   = BASE_CNT + (cta < 96 ? 1 : 0);
    const int start = BASE_CNT * cta + (cta < 96 ? cta : 96);
    const int row0  = start / WO;
    const int row1  = (start + cnt - 1) / WO;

    // ---- transpose w into smem: w_t[f][k] ----
    for (int idx = tid; idx < KK * NF; idx += NTHREADS) {
        int k = idx >> 6;        // /64
        int f = idx & 63;
        w_t[f * WT_STRIDE + k] = w[idx];
    }

    // ---- load up to 2 input row-triples (each contiguous 3*32*32 floats) ----
    #pragma unroll
    for (int s = 0; s < 2; s++) {
        int rf = s ? row1 : row0;
        int bb = rf / HO;
        int hh = rf - bb * HO;
        const float4* src = (const float4*)(x + (size_t)(bb * HH + hh) * (WW * CH));
        float4* dst = (float4*)(x_s + s * XSEG_FLOATS);
        for (int v = tid; v < XSEG_FLOATS / 4; v += NTHREADS)
            dst[v] = src[v];
    }
    __syncthreads();

    const int fg = tid & 7;        // filter group: f = fg + 8*l
    const int pp = tid >> 3;       // position slot 0..23

    float bi[8];
    #pragma unroll
    for (int l = 0; l < 8; l++)
        bi[l] = __ldg(bias + fg + 8 * l);

    const float* wt_base = w_t + fg * WT_STRIDE;

    for (int pos = start + pp; pos < start + cnt; pos += BASE_CNT) {
        int rowf = pos / WO;
        int wo   = pos - rowf * WO;
        int seg  = (rowf != row0) ? 1 : 0;
        const float* xb = x_s + seg * XSEG_FLOATS + wo * CH;

        float mx[8], mn[8];
        #pragma unroll
        for (int l = 0; l < 8; l++) { mx[l] = -FLT_MAX; mn[l] = FLT_MAX; }

        #pragma unroll 1
        for (int ij = 0; ij < KH * KW; ij++) {
            const int i = ij / 3;
            const int j = ij - i * 3;
            const float* pr = xb + (i * WW + j) * CH;
            const float* wr = wt_base + ij * CH;

            #pragma unroll
            for (int c = 0; c < CH; c += 4) {
                float4 p = *(const float4*)(pr + c);
                float2 pA = make_float2(p.x, p.y);
                float2 pB = make_float2(p.z, p.w);
                #pragma unroll
                for (int l = 0; l < 8; l++) {
                    float4 wv = *(const float4*)(wr + l * (8 * WT_STRIDE) + c);
                    float2 s01 = fadd2(pA, make_float2(wv.x, wv.y));
                    float2 s23 = fadd2(pB, make_float2(wv.z, wv.w));
                    mx[l] = fmaxf(mx[l], s01.x); mn[l] = fminf(mn[l], s01.x);
                    mx[l] = fmaxf(mx[l], s01.y); mn[l] = fminf(mn[l], s01.y);
                    mx[l] = fmaxf(mx[l], s23.x); mn[l] = fminf(mn[l], s23.x);
                    mx[l] = fmaxf(mx[l], s23.y); mn[l] = fminf(mn[l], s23.y);
                }
            }
        }

        float* o = out + (size_t)pos * NF + fg;
        #pragma unroll
        for (int l = 0; l < 8; l++)
            o[8 * l] = mx[l] - mn[l] + bi[l];
    }
}

extern "C" void kernel_launch(void* const* d_in, const int* in_sizes, int n_in,
                              void* d_out, int out_size)
{
    const float* x    = (const float*)d_in[0];
    const float* w    = (const float*)d_in[1];
    const float* bias = (const float*)d_in[2];
    float*       out  = (float*)d_out;

    cudaFuncSetAttribute(tropconv_kernel,
                         cudaFuncAttributeMaxDynamicSharedMemorySize, SMEM_BYTES);
    tropconv_kernel<<<NCTA, NTHREADS, SMEM_BYTES>>>(x, w, bias, out);
}

// round 4
// speedup vs baseline: 1.4040x; 1.4040x over previous
#include <cuda_runtime.h>
#include <float.h>

// TropConv2D: out[pos, f] = max_k(p_k + w[k][f]) - min_k(p_k + w[k][f]) + bias[f]
// pos flat over (b, ho, wo); p_k = x[b, ho+i, wo+j, c], k = (i*3+j)*32 + c
#define KH 3
#define KW 3
#define CH 32
#define NF 64
#define HH 32
#define WW 32
#define HO 30
#define WO 30
#define KK  (KH*KW*CH)       // 288

#define W_S_FLOATS (KK*NF)                  // 18432
#define XSEG_FLOATS (3*WW*CH)               // 3072 (one contiguous 3-row triple)
#define X_S_FLOATS (2*XSEG_FLOATS)          // 6144
#define SMEM_BYTES ((W_S_FLOATS + X_S_FLOATS)*4)   // 98304

#define NTHREADS 256
#define NCTA 296         // 2 * 148 -> exactly 2 CTAs per SM
#define BASE_CNT 24      // 96 CTAs get 25 positions, 200 get 24 (96*25+200*24=7200)

#define UPD4(P, WV, MX, MN) do {                                   \
    float s_;                                                      \
    s_ = (P) + (WV).x; (MX).x = fmaxf((MX).x, s_); (MN).x = fminf((MN).x, s_); \
    s_ = (P) + (WV).y; (MX).y = fmaxf((MX).y, s_); (MN).y = fminf((MN).y, s_); \
    s_ = (P) + (WV).z; (MX).z = fmaxf((MX).z, s_); (MN).z = fminf((MN).z, s_); \
    s_ = (P) + (WV).w; (MX).w = fmaxf((MX).w, s_); (MN).w = fminf((MN).w, s_); \
  } while (0)

__global__ __launch_bounds__(NTHREADS, 2)
void tropconv_kernel(const float* __restrict__ x,
                     const float* __restrict__ w,
                     const float* __restrict__ bias,
                     float* __restrict__ out)
{
    extern __shared__ float smem[];
    float* w_s = smem;                  // [KK][NF] k-major (as in gmem)
    float* x_s = smem + W_S_FLOATS;     // two contiguous [3][WW][CH] row-triples

    const int tid = threadIdx.x;
    const int cta = blockIdx.x;

    const int cnt   = BASE_CNT + (cta < 96 ? 1 : 0);
    const int start = BASE_CNT * cta + (cta < 96 ? cta : 96);
    const int row0  = start / WO;
    const int row1  = (start + cnt - 1) / WO;

    // ---- copy w (18432 floats = 4608 float4; 18 per thread) ----
    {
        const float4* wg  = (const float4*)w;
        float4*       ws4 = (float4*)w_s;
        #pragma unroll
        for (int i = 0; i < 18; i++)
            ws4[tid + NTHREADS * i] = wg[tid + NTHREADS * i];
    }
    // ---- load the 2 input row-triples (each a contiguous 3*32*32-float slab) ----
    #pragma unroll
    for (int s = 0; s < 2; s++) {
        int rf = s ? row1 : row0;
        int bb = rf / HO;
        int hh = rf - bb * HO;
        const float4* src = (const float4*)(x + (size_t)(bb * HH + hh) * (WW * CH));
        float4* dst = (float4*)(x_s + s * XSEG_FLOATS);
        #pragma unroll
        for (int v = 0; v < XSEG_FLOATS / 4 / NTHREADS; v++)       // 3 each
            dst[tid + NTHREADS * v] = src[tid + NTHREADS * v];
    }
    __syncthreads();

    // thread = (pp, fg): positions start+pp and start+16+pp, 4 filters f0..f0+3
    const int fg  = tid & 15;
    const int pp  = tid >> 4;          // 0..15
    const int f0  = fg * 4;

    const int pos0 = start + pp;                 // always < start+cnt (cnt>=24)
    const int pos1 = start + 16 + pp;
    const bool act1 = (16 + pp) < cnt;

    // position -> smem base pointer (wo*CH within the right row-triple)
    int r0 = pos0 / WO;
    int wo_0 = pos0 - r0 * WO;
    const float* xb0 = x_s + (r0 != row0 ? XSEG_FLOATS : 0) + wo_0 * CH;

    int r1 = pos1 / WO;
    int wo_1 = pos1 - r1 * WO;
    const float* xb1 = act1 ? (x_s + (r1 != row0 ? XSEG_FLOATS : 0) + wo_1 * CH)
                            : xb0;    // harmless dummy work for inactive slot

    float4 mx0 = make_float4(-FLT_MAX,-FLT_MAX,-FLT_MAX,-FLT_MAX);
    float4 mn0 = make_float4( FLT_MAX, FLT_MAX, FLT_MAX, FLT_MAX);
    float4 mx1 = mx0, mn1 = mn0;

    #pragma unroll 1
    for (int ij = 0; ij < KH * KW; ij++) {
        const int i = ij / 3;
        const int j = ij - i * 3;
        const float* pr0 = xb0 + (i * WW + j) * CH;
        const float* pr1 = xb1 + (i * WW + j) * CH;
        const float* wr  = w_s + (ij * CH) * NF + f0;
        #pragma unroll
        for (int c = 0; c < CH; c += 4) {
            float4 p0 = *(const float4*)(pr0 + c);
            float4 p1 = *(const float4*)(pr1 + c);
            float4 w0 = *(const float4*)(wr + (c+0)*NF);
            float4 w1 = *(const float4*)(wr + (c+1)*NF);
            float4 w2 = *(const float4*)(wr + (c+2)*NF);
            float4 w3 = *(const float4*)(wr + (c+3)*NF);
            UPD4(p0.x, w0, mx0, mn0);
            UPD4(p0.y, w1, mx0, mn0);
            UPD4(p0.z, w2, mx0, mn0);
            UPD4(p0.w, w3, mx0, mn0);
            UPD4(p1.x, w0, mx1, mn1);
            UPD4(p1.y, w1, mx1, mn1);
            UPD4(p1.z, w2, mx1, mn1);
            UPD4(p1.w, w3, mx1, mn1);
        }
    }

    const float4 bi = *(const float4*)(bias + f0);

    {
        float4 r;
        r.x = mx0.x - mn0.x + bi.x;
        r.y = mx0.y - mn0.y + bi.y;
        r.z = mx0.z - mn0.z + bi.z;
        r.w = mx0.w - mn0.w + bi.w;
        *(float4*)(out + (size_t)pos0 * NF + f0) = r;
    }
    if (act1) {
        float4 r;
        r.x = mx1.x - mn1.x + bi.x;
        r.y = mx1.y - mn1.y + bi.y;
        r.z = mx1.z - mn1.z + bi.z;
        r.w = mx1.w - mn1.w + bi.w;
        *(float4*)(out + (size_t)pos1 * NF + f0) = r;
    }
}

extern "C" void kernel_launch(void* const* d_in, const int* in_sizes, int n_in,
                              void* d_out, int out_size)
{
    const float* x    = (const float*)d_in[0];
    const float* w    = (const float*)d_in[1];
    const float* bias = (const float*)d_in[2];
    float*       out  = (float*)d_out;

    cudaFuncSetAttribute(tropconv_kernel,
                         cudaFuncAttributeMaxDynamicSharedMemorySize, SMEM_BYTES);
    tropconv_kernel<<<NCTA, NTHREADS, SMEM_BYTES>>>(x, w, bias, out);
}

// round 5
// speedup vs baseline: 1.9554x; 1.3928x over previous
#include <cuda_runtime.h>
#include <cuda_fp16.h>
#include <float.h>

// TropConv2D: out[pos,f] = max_k(p_k + w[k][f]) - min_k(p_k + w[k][f]) + bias[f]
// fp16x2 inner loop, filters paired (f even/odd in one half2), x pre-broadcast (p,p).
#define KH 3
#define KW 3
#define CH 32
#define NF 64
#define HH 32
#define WW 32
#define HO 30
#define WO 30
#define KK  (KH*KW*CH)          // 288

#define W_H2     (KK*(NF/2))    // 9216 half2 : w_h[k][f2]
#define XSEG_H2  (3*WW*CH)      // 3072 half2 : one 3-row triple, broadcast (p,p)
#define SMEM_H2  (W_H2 + 2*XSEG_H2)
#define SMEM_BYTES (SMEM_H2*4)  // 61440

#define NTHREADS 256
#define NCTA 296                // 2 * 148 -> exactly 2 CTAs per SM
#define BASE_CNT 24             // 96 CTAs get 25 positions, 200 get 24

struct alignas(16) h2x4 { __half2 a, b, c, d; };
struct alignas(8)  h2x2 { __half2 a, b; };

#define UPD2(PC, WV, MX, MN) do {                 \
    __half2 s_ = __hadd2((PC), (WV));             \
    (MX) = __hmax2((MX), s_);                     \
    (MN) = __hmin2((MN), s_);                     \
  } while (0)

// one channel, one position: two filter-pairs
#define UPDCH(PC, WP, MXa, MXb, MNa, MNb) do {    \
    UPD2((PC), (WP).a, (MXa), (MNa));             \
    UPD2((PC), (WP).b, (MXb), (MNb));             \
  } while (0)

__global__ __launch_bounds__(NTHREADS, 2)
void tropconv_kernel(const float* __restrict__ x,
                     const float* __restrict__ w,
                     const float* __restrict__ bias,
                     float* __restrict__ out)
{
    extern __shared__ __half2 smem[];
    __half2* w_h = smem;              // [KK][32] half2 filter-pairs
    __half2* x_h = smem + W_H2;       // [2][3*WW*CH] broadcast half2

    const int tid = threadIdx.x;
    const int cta = blockIdx.x;

    const int cnt   = BASE_CNT + (cta < 96 ? 1 : 0);
    const int start = BASE_CNT * cta + (cta < 96 ? cta : 96);
    const int row0  = start / WO;
    const int row1  = (start + cnt - 1) / WO;

    // ---- convert w -> half2 pairs in smem (4608 float4, 18/thread) ----
    {
        const float4* wg = (const float4*)w;
        #pragma unroll
        for (int i = 0; i < 18; i++) {
            int v = tid + NTHREADS * i;       // float4 idx: k = v>>4, quad = v&15
            float4 t = wg[v];
            h2x2 o;
            o.a = __floats2half2_rn(t.x, t.y);   // (f, f+1)
            o.b = __floats2half2_rn(t.z, t.w);   // (f+2, f+3)
            *(h2x2*)(w_h + ((v >> 4) * 32 + (v & 15) * 2)) = o;
        }
    }
    // ---- convert 2 input row-triples -> broadcast half2 (768 float4 each) ----
    #pragma unroll
    for (int s = 0; s < 2; s++) {
        int rf = s ? row1 : row0;
        int bb = rf / HO;
        int hh = rf - bb * HO;
        const float4* src = (const float4*)(x + (size_t)(bb * HH + hh) * (WW * CH));
        __half2* dst = x_h + s * XSEG_H2;
        #pragma unroll
        for (int i = 0; i < 3; i++) {
            int v = tid + NTHREADS * i;
            float4 t = src[v];
            h2x4 o;
            o.a = __floats2half2_rn(t.x, t.x);
            o.b = __floats2half2_rn(t.y, t.y);
            o.c = __floats2half2_rn(t.z, t.z);
            o.d = __floats2half2_rn(t.w, t.w);
            *(h2x4*)(dst + v * 4) = o;
        }
    }
    __syncthreads();

    // thread = (pp 0..15, fg 0..15): positions start+pp, start+16+pp; filters 4fg..4fg+3
    const int fg = tid & 15;
    const int pp = tid >> 4;
    const int f0 = fg * 4;

    const int  pos0 = start + pp;
    const int  pos1 = start + 16 + pp;
    const bool act1 = (16 + pp) < cnt;

    int r0 = pos0 / WO;
    int wo_0 = pos0 - r0 * WO;
    const __half2* xb0 = x_h + (r0 != row0 ? XSEG_H2 : 0) + wo_0 * CH;

    int r1 = pos1 / WO;
    int wo_1 = pos1 - r1 * WO;
    const __half2* xb1 = act1 ? (x_h + (r1 != row0 ? XSEG_H2 : 0) + wo_1 * CH)
                              : xb0;

    const __half2 NEG = __float2half2_rn(-65504.f);
    const __half2 POS = __float2half2_rn( 65504.f);
    __half2 mx00 = NEG, mx01 = NEG, mn00 = POS, mn01 = POS;
    __half2 mx10 = NEG, mx11 = NEG, mn10 = POS, mn11 = POS;

    #pragma unroll 1
    for (int ij = 0; ij < KH * KW; ij++) {
        const int i = ij / 3;
        const int j = ij - i * 3;
        const h2x4* pr0 = (const h2x4*)(xb0 + (i * WW + j) * CH);
        const h2x4* pr1 = (const h2x4*)(xb1 + (i * WW + j) * CH);
        const __half2* wr = w_h + ij * CH * 32 + fg * 2;

        #pragma unroll
        for (int c = 0; c < CH; c += 4) {
            h2x4 P0 = pr0[c >> 2];
            h2x4 P1 = pr1[c >> 2];
            h2x2 W0 = *(const h2x2*)(wr + (c + 0) * 32);
            h2x2 W1 = *(const h2x2*)(wr + (c + 1) * 32);
            h2x2 W2 = *(const h2x2*)(wr + (c + 2) * 32);
            h2x2 W3 = *(const h2x2*)(wr + (c + 3) * 32);

            UPDCH(P0.a, W0, mx00, mx01, mn00, mn01);
            UPDCH(P0.b, W1, mx00, mx01, mn00, mn01);
            UPDCH(P0.c, W2, mx00, mx01, mn00, mn01);
            UPDCH(P0.d, W3, mx00, mx01, mn00, mn01);
            UPDCH(P1.a, W0, mx10, mx11, mn10, mn11);
            UPDCH(P1.b, W1, mx10, mx11, mn10, mn11);
            UPDCH(P1.c, W2, mx10, mx11, mn10, mn11);
            UPDCH(P1.d, W3, mx10, mx11, mn10, mn11);
        }
    }

    const float4 bi = *(const float4*)(bias + f0);

    {
        float2 a = __half22float2(mx00), b = __half22float2(mn00);
        float2 c = __half22float2(mx01), d = __half22float2(mn01);
        float4 r;
        r.x = a.x - b.x + bi.x;
        r.y = a.y - b.y + bi.y;
        r.z = c.x - d.x + bi.z;
        r.w = c.y - d.y + bi.w;
        *(float4*)(out + (size_t)pos0 * NF + f0) = r;
    }
    if (act1) {
        float2 a = __half22float2(mx10), b = __half22float2(mn10);
        float2 c = __half22float2(mx11), d = __half22float2(mn11);
        float4 r;
        r.x = a.x - b.x + bi.x;
        r.y = a.y - b.y + bi.y;
        r.z = c.x - d.x + bi.z;
        r.w = c.y - d.y + bi.w;
        *(float4*)(out + (size_t)pos1 * NF + f0) = r;
    }
}

extern "C" void kernel_launch(void* const* d_in, const int* in_sizes, int n_in,
                              void* d_out, int out_size)
{
    const float* x    = (const float*)d_in[0];
    const float* w    = (const float*)d_in[1];
    const float* bias = (const float*)d_in[2];
    float*       out  = (float*)d_out;

    cudaFuncSetAttribute(tropconv_kernel,
                         cudaFuncAttributeMaxDynamicSharedMemorySize, SMEM_BYTES);
    tropconv_kernel<<<NCTA, NTHREADS, SMEM_BYTES>>>(x, w, bias, out);
}